// round 10
// baseline (speedup 1.0000x reference)
#include <cuda_runtime.h>
#include <cuda_bf16.h>
#include <cstdint>

// YOLO loss: N=64, S=128, B=2.
// input (N,S,S,10) fp32, target (N,S,S,5) fp32 -> 5 fp32 scalars.
// 512 blocks x 256 threads; 8 tiles of 256 cells per block streamed through a
// 3-stage cp.async ring (prefetch distance 2, ONE barrier per tile).

#define NCELLS (64 * 128 * 128)
#define THREADS 256
#define NWARPS (THREADS / 32)
#define TILE 256
#define TILES_PER_BLOCK 8
#define BLOCKS (NCELLS / (TILE * TILES_PER_BLOCK))   // 512
#define STAGES 3

#define IN_F4_PER_TILE (TILE * 10 / 4)   // 640 float4
#define TG_F4_PER_TILE (TILE * 5 / 4)    // 320 float4

__device__ float g_acc[6];   // 0:S_noobj 1:S_xy 2:S_wh 3:S_obj 4:S_nresp 5:m
__device__ unsigned int g_count;

__device__ __forceinline__ float softplus_fast(float x) {
    return fmaxf(x, 0.0f) + __logf(1.0f + __expf(-fabsf(x)));
}
__device__ __forceinline__ float sigmoid_fast(float x) {
    return __fdividef(1.0f, 1.0f + __expf(-x));
}
__device__ __forceinline__ void cp_async16(unsigned int smem_addr, const void* gptr) {
    asm volatile("cp.async.cg.shared.global [%0], [%1], 16;"
                 :: "r"(smem_addr), "l"(gptr) : "memory");
}

// Branchless single-cell processing.
__device__ __forceinline__ void process_cell(
    float l0, float x0, float y0, float w0, float h0,
    float l1, float x1, float y1, float w1, float h1,
    float tconf, float tx, float ty, float tw, float th,
    float& s_noobj, float& s_xy, float& s_wh,
    float& s_obj, float& s_nresp, float& s_m)
{
    float obj = (tconf > 0.0f) ? 1.0f : 0.0f;
    float noobj = 1.0f - obj;

    float bce0_0 = softplus_fast(l0);
    float bce0_1 = softplus_fast(l1);

    s_noobj += noobj * (bce0_0 + bce0_1);
    s_m += obj;

    float c0x = sigmoid_fast(x0), c0y = sigmoid_fast(y0);
    float c0w = sigmoid_fast(w0), c0h = sigmoid_fast(h0);
    float c1x = sigmoid_fast(x1), c1y = sigmoid_fast(y1);
    float c1w = sigmoid_fast(w1), c1h = sigmoid_fast(h1);

    float tlx = tx - tw * 0.5f, tly = ty - th * 0.5f;
    float trx = tx + tw * 0.5f, trY = ty + th * 0.5f;
    float area_t = tw * th;

    float wx0 = fmaxf(0.0f, fminf(c0x + c0w * 0.5f, trx) - fmaxf(c0x - c0w * 0.5f, tlx));
    float wy0 = fmaxf(0.0f, fminf(c0y + c0h * 0.5f, trY) - fmaxf(c0y - c0h * 0.5f, tly));
    float inter0 = wx0 * wy0;
    float den0 = c0w * c0h + area_t - inter0 + 1e-10f;

    float wx1 = fmaxf(0.0f, fminf(c1x + c1w * 0.5f, trx) - fmaxf(c1x - c1w * 0.5f, tlx));
    float wy1 = fmaxf(0.0f, fminf(c1y + c1h * 0.5f, trY) - fmaxf(c1y - c1h * 0.5f, tly));
    float inter1 = wx1 * wy1;
    float den1 = c1w * c1h + area_t - inter1 + 1e-10f;

    // argmax(iou): box1 wins iff strictly greater (first-max tie-break);
    // denominators > 0 -> cross-product compare, no division.
    bool r1 = inter1 * den0 > inter0 * den1;

    float rx = r1 ? c1x : c0x, ry = r1 ? c1y : c0y;
    float rw = r1 ? c1w : c0w, rh = r1 ? c1h : c0h;
    float rl = r1 ? l1 : l0;
    float rb = r1 ? bce0_1 : bce0_0;
    float nb = r1 ? bce0_0 : bce0_1;

    float dx = rx - tx, dy = ry - ty, dw = rw - tw, dh = rh - th;
    s_xy    += obj * (dx * dx + dy * dy);
    s_wh    += obj * (dw * dw + dh * dh);
    s_obj   += obj * (rb - rl);
    s_nresp += obj * nb;
}

__shared__ union __align__(16) SmemU {
    struct {
        float in[STAGES][TILE * 10];   // 3 x 10 KB
        float tg[STAGES][TILE * 5];    // 3 x 5 KB
    } pipe;                            // 45 KB
    float red[6][THREADS];             // 6 KB (reused after pipeline drains)
} sm;

__global__ void __launch_bounds__(THREADS)
yolo_fused_kernel(const float* __restrict__ inp, const float* __restrict__ tgt,
                  float* __restrict__ out) {
    int tid = threadIdx.x;
    size_t cell0 = (size_t)blockIdx.x * (TILE * TILES_PER_BLOCK);
    const float* gin = inp + cell0 * 10;
    const float* gtg = tgt + cell0 * 5;

    // prefetch tile t into ring stage (coalesced 16B cp.async, one commit/tile)
    auto prefetch = [&](int t) {
        int stage = t % STAGES;
        unsigned int ia = (unsigned int)__cvta_generic_to_shared(sm.pipe.in[stage]);
        unsigned int ta = (unsigned int)__cvta_generic_to_shared(sm.pipe.tg[stage]);
        const float* gi = gin + (size_t)t * TILE * 10;
        const float* gt = gtg + (size_t)t * TILE * 5;
#pragma unroll
        for (int i = 0; i < 2; i++) {                      // 512 of 640 float4
            int idx = tid + i * THREADS;
            cp_async16(ia + idx * 16, gi + idx * 4);
        }
        {
            int idx = tid + 2 * THREADS;                   // remaining 128
            if (idx < IN_F4_PER_TILE)
                cp_async16(ia + idx * 16, gi + idx * 4);
        }
        {
            int idx = tid;                                 // 256 of 320 float4
            cp_async16(ta + idx * 16, gt + idx * 4);
            idx = tid + THREADS;                           // remaining 64
            if (idx < TG_F4_PER_TILE)
                cp_async16(ta + idx * 16, gt + idx * 4);
        }
        asm volatile("cp.async.commit_group;" ::: "memory");
    };

    float s_noobj = 0.0f, s_xy = 0.0f, s_wh = 0.0f;
    float s_obj = 0.0f, s_nresp = 0.0f, s_m = 0.0f;

    // prologue: fill 2 stages
    prefetch(0);
    prefetch(1);

#pragma unroll
    for (int t = 0; t < TILES_PER_BLOCK; t++) {
        int stage = t % STAGES;

        // wait for tile t's group (keep the next one in flight)
        if (t + 1 < TILES_PER_BLOCK)
            asm volatile("cp.async.wait_group 1;" ::: "memory");
        else
            asm volatile("cp.async.wait_group 0;" ::: "memory");

        // single barrier per tile: orders (a) tile t data visible to all,
        // (b) all reads of stage (t-1)%3 complete -> prefetch(t+2) may
        // overwrite it ((t+2)%3 == (t-1)%3).
        __syncthreads();

        if (t + 2 < TILES_PER_BLOCK)
            prefetch(t + 2);

        // process 1 cell per thread from smem
        const float2* ip = reinterpret_cast<const float2*>(sm.pipe.in[stage] + tid * 10);
        float2 a0 = ip[0], a1 = ip[1], a2 = ip[2], a3 = ip[3], a4 = ip[4];
        const float* tp = sm.pipe.tg[stage] + tid * 5;
        float tconf = tp[0], tx = tp[1], ty = tp[2], tw = tp[3], th = tp[4];

        process_cell(a0.x, a0.y, a1.x, a1.y, a2.x,
                     a2.y, a3.x, a3.y, a4.x, a4.y,
                     tconf, tx, ty, tw, th,
                     s_noobj, s_xy, s_wh, s_obj, s_nresp, s_m);
    }

    // ---- block reduction via smem transpose (reuse pipeline smem) ----
    __syncthreads();   // all compute done before overwriting smem
    sm.red[0][tid] = s_noobj;
    sm.red[1][tid] = s_xy;
    sm.red[2][tid] = s_wh;
    sm.red[3][tid] = s_obj;
    sm.red[4][tid] = s_nresp;
    sm.red[5][tid] = s_m;
    __syncthreads();

    int lane = tid & 31;
    int warp = tid >> 5;
    if (warp < 6) {
        float v = 0.0f;
#pragma unroll
        for (int j = 0; j < THREADS / 32; j++)
            v += sm.red[warp][lane + j * 32];
#pragma unroll
        for (int off = 16; off > 0; off >>= 1)
            v += __shfl_xor_sync(0xffffffffu, v, off);
        if (lane == 0)
            atomicAdd(&g_acc[warp], v);
    }
    __syncthreads();

    // ---- last block finalizes + resets for the next graph replay ----
    if (tid == 0) {
        __threadfence();
        unsigned int old = atomicAdd(&g_count, 1u);
        if (old == (unsigned int)(gridDim.x - 1)) {
            volatile float* ga = g_acc;
            float a_noobj = ga[0], a_xy = ga[1], a_wh = ga[2];
            float a_obj = ga[3], a_nresp = ga[4], m = ga[5];
            float n_noobj = (float)NCELLS - m;
            float loss_noobj = a_noobj / (n_noobj * 2.0f) + a_nresp / m;  // B=2
            float loss_xy = a_xy / (m * 2.0f);
            float loss_wh = a_wh / (m * 2.0f);
            float loss_obj = a_obj / m;
            out[0] = loss_noobj + loss_xy + loss_wh + loss_obj;
            out[1] = loss_noobj;
            out[2] = loss_xy;
            out[3] = loss_wh;
            out[4] = loss_obj;
#pragma unroll
            for (int k = 0; k < 6; k++) g_acc[k] = 0.0f;
            g_count = 0u;
        }
    }
}

extern "C" void kernel_launch(void* const* d_in, const int* in_sizes, int n_in,
                              void* d_out, int out_size) {
    const float* inp = (const float*)d_in[0];
    const float* tgt = (const float*)d_in[1];
    float* out = (float*)d_out;
    yolo_fused_kernel<<<BLOCKS, THREADS>>>(inp, tgt, out);
}